// round 16
// baseline (speedup 1.0000x reference)
#include <cuda_runtime.h>
#include <cuda_fp16.h>
#include <cstdint>
#include <math.h>

#define B_ 2
#define T_ 2048
#define D_ 1024
#define H_ 16
#define HD 64
#define P_ 256
#define NPASS_ 3
#define BT (B_ * T_)          // 4096

// ---------------- scratch (device globals; allocation-free) ----------------
__device__ __align__(16) half g_h16[BT * D_];          // rmsnorm1 out (fp16)
__device__ __align__(16) half g_w16[4 * D_ * D_];      // qkv_w (3DD) then o_w (DD), fp16
__device__ __align__(16) half g_qkv16[BT * 3 * D_];    // qkv projections fp16
__device__ __align__(16) half g_att16[BT * D_];        // attention out fp16
__device__ __align__(16) float g_x2[BT * D_];          // x + attn@o_w^T
__device__ __align__(16) float g_trig[2 * NPASS_ * P_]; // cos then sin per pass

// ---------------- helpers ----------------
__device__ __forceinline__ uint32_t smem_u32(const void* p) {
    return (uint32_t)__cvta_generic_to_shared(p);
}
__device__ __forceinline__ void ldm_x4(uint32_t& r0, uint32_t& r1, uint32_t& r2,
                                       uint32_t& r3, uint32_t addr) {
    asm volatile("ldmatrix.sync.aligned.m8n8.x4.shared.b16 {%0,%1,%2,%3},[%4];"
                 : "=r"(r0), "=r"(r1), "=r"(r2), "=r"(r3) : "r"(addr));
}
__device__ __forceinline__ void ldm_x4_t(uint32_t& r0, uint32_t& r1, uint32_t& r2,
                                         uint32_t& r3, uint32_t addr) {
    asm volatile("ldmatrix.sync.aligned.m8n8.x4.trans.shared.b16 {%0,%1,%2,%3},[%4];"
                 : "=r"(r0), "=r"(r1), "=r"(r2), "=r"(r3) : "r"(addr));
}
__device__ __forceinline__ void mma16816(float* c, const uint32_t* a, const uint32_t* b) {
    asm volatile(
        "mma.sync.aligned.m16n8k16.row.col.f32.f16.f16.f32 "
        "{%0,%1,%2,%3},{%4,%5,%6,%7},{%8,%9},{%0,%1,%2,%3};"
        : "+f"(c[0]), "+f"(c[1]), "+f"(c[2]), "+f"(c[3])
        : "r"(a[0]), "r"(a[1]), "r"(a[2]), "r"(a[3]), "r"(b[0]), "r"(b[1]));
}
__device__ __forceinline__ uint32_t h2u(float a, float b) {
    half2 h = __floats2half2_rn(a, b);
    uint32_t u;
    asm volatile("mov.b32 %0, %1;" : "=r"(u) : "r"(*reinterpret_cast<uint32_t*>(&h)));
    return u;
}
// single-MUFU base-2 exponential
__device__ __forceinline__ float ex2(float x) {
    float y;
    asm("ex2.approx.ftz.f32 %0, %1;" : "=f"(y) : "f"(x));
    return y;
}
__device__ __forceinline__ void cp16(uint32_t dst, const void* src) {
    asm volatile("cp.async.cg.shared.global [%0], [%1], 16;"
                 :: "r"(dst), "l"(src) : "memory");
}
__device__ __forceinline__ void cp16ca(uint32_t dst, const void* src) {
    asm volatile("cp.async.ca.shared.global [%0], [%1], 16;"
                 :: "r"(dst), "l"(src) : "memory");
}
__device__ __forceinline__ void cp_commit() {
    asm volatile("cp.async.commit_group;" ::: "memory");
}
template <int N>
__device__ __forceinline__ void cp_wait() {
    asm volatile("cp.async.wait_group %0;" :: "n"(N) : "memory");
}

// ---------------- precompute trig tables (768 sincosf total) ----------------
__global__ __launch_bounds__(256)
void trig_kernel(const float* __restrict__ angles, float* __restrict__ trig) {
    const int i = threadIdx.x;
#pragma unroll
    for (int p = 0; p < NPASS_; p++) {
        float sa, ca;
        sincosf(angles[p * P_ + i], &sa, &ca);
        trig[p * (2 * P_) + i] = ca;
        trig[p * (2 * P_) + P_ + i] = sa;
    }
}

// ---------------- f32 -> f16 conversion (weights) ----------------
__global__ __launch_bounds__(256)
void f2h4_kernel(const float* __restrict__ in, half* __restrict__ out, int n4) {
    int i = blockIdx.x * 256 + threadIdx.x;
    if (i < n4) {
        float4 v = ((const float4*)in)[i];
        half2* o = (half2*)out + i * 2;
        o[0] = __floats2half2_rn(v.x, v.y);
        o[1] = __floats2half2_rn(v.z, v.w);
    }
}

// ---------------- rmsnorm1 (+ gamma/beta), fp32 in, fp16 out ----------------
__global__ __launch_bounds__(256)
void rmsnorm_kernel(const float* __restrict__ x, const float* __restrict__ w,
                    const float* __restrict__ gamma, const float* __restrict__ beta,
                    half* __restrict__ out) {
    const int row = blockIdx.x;
    const int tid = threadIdx.x;
    const float* xr = x + (size_t)row * D_;
    float v[4];
    float ss = 0.f;
#pragma unroll
    for (int i = 0; i < 4; i++) {
        v[i] = xr[tid + i * 256];
        ss += v[i] * v[i];
    }
    __shared__ float red[8];
#pragma unroll
    for (int o = 16; o > 0; o >>= 1) ss += __shfl_xor_sync(0xffffffffu, ss, o);
    if ((tid & 31) == 0) red[tid >> 5] = ss;
    __syncthreads();
    if (tid < 8) {
        float s = red[tid];
#pragma unroll
        for (int o = 4; o > 0; o >>= 1) s += __shfl_xor_sync(0xffu, s, o);
        if (tid == 0) red[0] = s;
    }
    __syncthreads();
    const float rs = rsqrtf(red[0] * (1.0f / D_) + 1.1920929e-07f);
    half* op = out + (size_t)row * D_;
#pragma unroll
    for (int i = 0; i < 4; i++) {
        const int d = tid + i * 256;
        op[d] = (half)(v[i] * rs * w[d] * gamma[d] + beta[d]);
    }
}

// ---------------- fp16 NT GEMM with cp.async.ca 4-stage pipeline ------------
#define SA 40
#define GS 4
#define GT_SMEM (2 * GS * 128 * SA * 2)   // 81920 B
template <bool HALF_OUT, bool ADD_X>
__global__ __launch_bounds__(128, 2)
void gemm16_kernel(const half* __restrict__ A, const half* __restrict__ Bw,
                   const float* __restrict__ X, void* __restrict__ Cout,
                   int N, int K) {
    extern __shared__ char dsm[];
    half (*As)[128][SA] = (half(*)[128][SA])dsm;
    half (*Bs)[128][SA] = (half(*)[128][SA])(dsm + GS * 128 * SA * 2);
    const int tid = threadIdx.x, lane = tid & 31, w = tid >> 5;
    const int m0 = blockIdx.y * 128, n0 = blockIdx.x * 128;
    const int wm = (w >> 1) * 64, wn = (w & 1) * 64;
    const int lr = tid >> 1;
    const int lc = (tid & 1) * 16;
    const half* Ag0 = A + (size_t)(m0 + lr) * K + lc;
    const half* Ag1 = A + (size_t)(m0 + lr + 64) * K + lc;
    const half* Bg0 = Bw + (size_t)(n0 + lr) * K + lc;
    const half* Bg1 = Bw + (size_t)(n0 + lr + 64) * K + lc;

    auto issue = [&](int t) {
        const int s = t & (GS - 1);
        const int ko = t * 32;
        const uint32_t a0 = smem_u32(&As[s][lr][lc]);
        const uint32_t a1 = smem_u32(&As[s][lr + 64][lc]);
        const uint32_t b0 = smem_u32(&Bs[s][lr][lc]);
        const uint32_t b1 = smem_u32(&Bs[s][lr + 64][lc]);
        cp16ca(a0, Ag0 + ko);
        cp16ca(a0 + 16, Ag0 + ko + 8);
        cp16ca(a1, Ag1 + ko);
        cp16ca(a1 + 16, Ag1 + ko + 8);
        cp16ca(b0, Bg0 + ko);
        cp16ca(b0 + 16, Bg0 + ko + 8);
        cp16ca(b1, Bg1 + ko);
        cp16ca(b1 + 16, Bg1 + ko + 8);
    };

    float acc[4][8][4];
#pragma unroll
    for (int i = 0; i < 4; i++) {
#pragma unroll
        for (int j = 0; j < 8; j++) {
#pragma unroll
            for (int e = 0; e < 4; e++) acc[i][j][e] = 0.f;
        }
    }

    const int kt = K >> 5;
#pragma unroll
    for (int i = 0; i < GS - 1; i++) {
        issue(i);
        cp_commit();
    }

    for (int t = 0; t < kt; t++) {
        cp_wait<GS - 2>();
        __syncthreads();
        if (t + GS - 1 < kt) issue(t + GS - 1);
        cp_commit();
        const int cur = t & (GS - 1);
#pragma unroll
        for (int kk = 0; kk < 32; kk += 16) {
            uint32_t af[4][4];
            uint32_t bf[8][2];
#pragma unroll
            for (int mf = 0; mf < 4; mf++) {
                const int row = wm + mf * 16 + (lane & 15);
                const int col = kk + ((lane >> 4) << 3);
                ldm_x4(af[mf][0], af[mf][1], af[mf][2], af[mf][3],
                       smem_u32(&As[cur][row][col]));
            }
#pragma unroll
            for (int nf4 = 0; nf4 < 4; nf4++) {
                const int row = wn + nf4 * 16 + ((lane >> 4) << 3) + (lane & 7);
                const int col = kk + (((lane >> 3) & 1) << 3);
                uint32_t r0, r1, r2, r3;
                ldm_x4(r0, r1, r2, r3, smem_u32(&Bs[cur][row][col]));
                bf[nf4 * 2][0] = r0;
                bf[nf4 * 2][1] = r1;
                bf[nf4 * 2 + 1][0] = r2;
                bf[nf4 * 2 + 1][1] = r3;
            }
#pragma unroll
            for (int mf = 0; mf < 4; mf++) {
#pragma unroll
                for (int nf = 0; nf < 8; nf++) mma16816(acc[mf][nf], af[mf], bf[nf]);
            }
        }
    }

    const int r_lo = lane >> 2;
    const int c_off = (lane & 3) * 2;
#pragma unroll
    for (int mf = 0; mf < 4; mf++) {
        const int gr0 = m0 + wm + mf * 16 + r_lo;
        const int gr1 = gr0 + 8;
#pragma unroll
        for (int nf = 0; nf < 8; nf++) {
            const int gc = n0 + wn + nf * 8 + c_off;
            if constexpr (HALF_OUT) {
                half* C = (half*)Cout;
                *(half2*)(C + (size_t)gr0 * N + gc) =
                    __floats2half2_rn(acc[mf][nf][0], acc[mf][nf][1]);
                *(half2*)(C + (size_t)gr1 * N + gc) =
                    __floats2half2_rn(acc[mf][nf][2], acc[mf][nf][3]);
            } else {
                float* C = (float*)Cout;
                float v0 = acc[mf][nf][0];
                float v1 = acc[mf][nf][1];
                float v2 = acc[mf][nf][2];
                float v3 = acc[mf][nf][3];
                if constexpr (ADD_X) {
                    float2 x0 = *(const float2*)(X + (size_t)gr0 * N + gc);
                    float2 x1 = *(const float2*)(X + (size_t)gr1 * N + gc);
                    v0 += x0.x; v1 += x0.y; v2 += x1.x; v3 += x1.y;
                }
                *(float2*)(C + (size_t)gr0 * N + gc) = make_float2(v0, v1);
                *(float2*)(C + (size_t)gr1 * N + gc) = make_float2(v2, v3);
            }
        }
    }
}

// ---------------- fp16 causal flash attention, cp.async KV prefetch --------
#define AT_Q 0
#define AT_K 18432
#define AT_V 36864
#define AT_SMEM 55296
#define AT_ROWB 144            // 72 halfs * 2B
#define SC_LOG2E 0.1803368801111244f   // 0.125 * log2(e)

__global__ __launch_bounds__(256)
void attn16_kernel(const half* __restrict__ qkv, half* __restrict__ attno) {
    extern __shared__ char dsm[];
    const uint32_t sb = smem_u32(dsm);
    const int tid = threadIdx.x, lane = tid & 31, w = tid >> 5;
    const int q0 = blockIdx.x * 128;
    const int b = blockIdx.y >> 4, h = blockIdx.y & 15;
    const size_t rstride = 3 * D_;
    const half* qbase = qkv + (size_t)b * T_ * rstride + h * HD;

    auto issue_kv = [&](int t) {
        const int s = t & 1;
        const int k0 = t * 64;
#pragma unroll
        for (int i = 0; i < 2; i++) {
            const int idx = tid + i * 256;
            const int r = idx >> 3;
            const int c = (idx & 7) * 8;
            const half* kp = qbase + (size_t)(k0 + r) * rstride + D_ + c;
            cp16(sb + AT_K + s * 9216 + r * AT_ROWB + c * 2, kp);
            cp16(sb + AT_V + s * 9216 + r * AT_ROWB + c * 2, kp + D_);
        }
    };

#pragma unroll
    for (int i = 0; i < 4; i++) {
        const int idx = tid + i * 256;
        const int r = idx >> 3;
        const int c = (idx & 7) * 8;
        cp16(sb + AT_Q + r * AT_ROWB + c * 2,
             qbase + (size_t)(q0 + r) * rstride + c);
    }
    issue_kv(0);
    cp_commit();
    cp_wait<0>();
    __syncthreads();

    uint32_t qf[4][4];
    const int qrow = w * 16 + (lane & 15);
#pragma unroll
    for (int kk = 0; kk < 4; kk++) {
        const int col = kk * 16 + ((lane >> 4) << 3);
        ldm_x4(qf[kk][0], qf[kk][1], qf[kk][2], qf[kk][3],
               sb + AT_Q + qrow * AT_ROWB + col * 2);
    }

    float of[8][4];
#pragma unroll
    for (int nf = 0; nf < 8; nf++) {
#pragma unroll
        for (int e = 0; e < 4; e++) of[nf][e] = 0.f;
    }
    float m0 = -1e30f, m1 = -1e30f, l0 = 0.f, l1 = 0.f;
    const int r_lo = lane >> 2;
    const int c_off = (lane & 3) * 2;
    const int row0 = q0 + w * 16 + r_lo;

    const int nk = (q0 + 128) >> 6;
    for (int it = 0; it < nk; it++) {
        if (it > 0) {
            cp_wait<0>();
            __syncthreads();
        }
        if (it + 1 < nk) issue_kv(it + 1);
        cp_commit();
        const uint32_t kbase = sb + AT_K + (it & 1) * 9216;
        const uint32_t vbase = sb + AT_V + (it & 1) * 9216;
        const int k0 = it * 64;

        float sf[8][4];
#pragma unroll
        for (int nf = 0; nf < 8; nf++) {
#pragma unroll
            for (int e = 0; e < 4; e++) sf[nf][e] = 0.f;
        }
#pragma unroll
        for (int kk = 0; kk < 4; kk++) {
            uint32_t kf[8][2];
#pragma unroll
            for (int nf4 = 0; nf4 < 4; nf4++) {
                const int row = nf4 * 16 + ((lane >> 4) << 3) + (lane & 7);
                const int col = kk * 16 + (((lane >> 3) & 1) << 3);
                uint32_t r0, r1, r2, r3;
                ldm_x4(r0, r1, r2, r3, kbase + row * AT_ROWB + col * 2);
                kf[nf4 * 2][0] = r0;
                kf[nf4 * 2][1] = r1;
                kf[nf4 * 2 + 1][0] = r2;
                kf[nf4 * 2 + 1][1] = r3;
            }
#pragma unroll
            for (int nf = 0; nf < 8; nf++) mma16816(sf[nf], qf[kk], kf[nf]);
        }

        const bool domask = (k0 + 63 > row0);
#pragma unroll
        for (int nf = 0; nf < 8; nf++) {
#pragma unroll
            for (int e = 0; e < 4; e++) sf[nf][e] *= SC_LOG2E;
            if (domask) {
                const int col = k0 + nf * 8 + c_off;
                if (col > row0) sf[nf][0] = -1e30f;
                if (col + 1 > row0) sf[nf][1] = -1e30f;
                if (col > row0 + 8) sf[nf][2] = -1e30f;
                if (col + 1 > row0 + 8) sf[nf][3] = -1e30f;
            }
        }

        float mt0 = -1e30f, mt1 = -1e30f;
#pragma unroll
        for (int nf = 0; nf < 8; nf++) {
            mt0 = fmaxf(mt0, fmaxf(sf[nf][0], sf[nf][1]));
            mt1 = fmaxf(mt1, fmaxf(sf[nf][2], sf[nf][3]));
        }
        mt0 = fmaxf(mt0, __shfl_xor_sync(0xffffffffu, mt0, 1));
        mt0 = fmaxf(mt0, __shfl_xor_sync(0xffffffffu, mt0, 2));
        mt1 = fmaxf(mt1, __shfl_xor_sync(0xffffffffu, mt1, 1));
        mt1 = fmaxf(mt1, __shfl_xor_sync(0xffffffffu, mt1, 2));
        const float mn0 = fmaxf(m0, mt0);
        const float mn1 = fmaxf(m1, mt1);
        const float al0 = ex2(m0 - mn0);
        const float al1 = ex2(m1 - mn1);
        m0 = mn0;
        m1 = mn1;
        float rs0 = 0.f, rs1 = 0.f;
#pragma unroll
        for (int nf = 0; nf < 8; nf++) {
            sf[nf][0] = ex2(sf[nf][0] - mn0);
            sf[nf][1] = ex2(sf[nf][1] - mn0);
            sf[nf][2] = ex2(sf[nf][2] - mn1);
            sf[nf][3] = ex2(sf[nf][3] - mn1);
            rs0 += sf[nf][0] + sf[nf][1];
            rs1 += sf[nf][2] + sf[nf][3];
        }
        l0 = l0 * al0 + rs0;
        l1 = l1 * al1 + rs1;
#pragma unroll
        for (int nf = 0; nf < 8; nf++) {
            of[nf][0] *= al0;
            of[nf][1] *= al0;
            of[nf][2] *= al1;
            of[nf][3] *= al1;
        }

        uint32_t pf[4][4];
#pragma unroll
        for (int kk = 0; kk < 4; kk++) {
            pf[kk][0] = h2u(sf[2 * kk][0], sf[2 * kk][1]);
            pf[kk][1] = h2u(sf[2 * kk][2], sf[2 * kk][3]);
            pf[kk][2] = h2u(sf[2 * kk + 1][0], sf[2 * kk + 1][1]);
            pf[kk][3] = h2u(sf[2 * kk + 1][2], sf[2 * kk + 1][3]);
        }

#pragma unroll
        for (int kk = 0; kk < 4; kk++) {
            uint32_t vf[8][2];
#pragma unroll
            for (int nf4 = 0; nf4 < 4; nf4++) {
                const int row = kk * 16 + (lane & 15);
                const int col = nf4 * 16 + ((lane >> 4) << 3);
                uint32_t r0, r1, r2, r3;
                ldm_x4_t(r0, r1, r2, r3, vbase + row * AT_ROWB + col * 2);
                vf[nf4 * 2][0] = r0;
                vf[nf4 * 2][1] = r1;
                vf[nf4 * 2 + 1][0] = r2;
                vf[nf4 * 2 + 1][1] = r3;
            }
#pragma unroll
            for (int nf = 0; nf < 8; nf++) mma16816(of[nf], pf[kk], vf[nf]);
        }
    }

    l0 += __shfl_xor_sync(0xffffffffu, l0, 1);
    l0 += __shfl_xor_sync(0xffffffffu, l0, 2);
    l1 += __shfl_xor_sync(0xffffffffu, l1, 1);
    l1 += __shfl_xor_sync(0xffffffffu, l1, 2);

    const float inv0 = 1.f / l0;
    const float inv1 = 1.f / l1;
    half* obase = attno + h * HD;
#pragma unroll
    for (int nf = 0; nf < 8; nf++) {
        const int c = nf * 8 + c_off;
        *(half2*)(obase + ((size_t)b * T_ + row0) * D_ + c) =
            __floats2half2_rn(of[nf][0] * inv0, of[nf][1] * inv0);
        *(half2*)(obase + ((size_t)b * T_ + row0 + 8) * D_ + c) =
            __floats2half2_rn(of[nf][2] * inv1, of[nf][3] * inv1);
    }
}

// ------- fused rmsnorm2 + rotation passes + silu + final combine -----------
// Trig from precomputed table (no sincosf in the hot path).
__global__ __launch_bounds__(256)
void rmsrot_kernel(const float* __restrict__ x2, const float* __restrict__ w,
                   const float* __restrict__ gamma, const float* __restrict__ beta,
                   const float* __restrict__ trig, const float* __restrict__ gate,
                   const float* __restrict__ bias, const int* __restrict__ pi,
                   const int* __restrict__ pj, float* __restrict__ out) {
    const int row = blockIdx.x;
    const int tid = threadIdx.x;
    __shared__ float r[D_];
    __shared__ float red[8];
    const float* xrow = x2 + (size_t)row * D_;

    float v[4];
    float ss = 0.f;
#pragma unroll
    for (int i = 0; i < 4; i++) {
        v[i] = xrow[tid + i * 256];
        ss += v[i] * v[i];
    }
#pragma unroll
    for (int o = 16; o > 0; o >>= 1) ss += __shfl_xor_sync(0xffffffffu, ss, o);
    if ((tid & 31) == 0) red[tid >> 5] = ss;
    __syncthreads();
    if (tid < 8) {
        float s = red[tid];
#pragma unroll
        for (int o = 4; o > 0; o >>= 1) s += __shfl_xor_sync(0xffu, s, o);
        if (tid == 0) red[0] = s;
    }
    __syncthreads();
    const float rs = rsqrtf(red[0] * (1.0f / D_) + 1.1920929e-07f);

    float hreg[4];
#pragma unroll
    for (int i = 0; i < 4; i++) {
        const int d = tid + i * 256;
        hreg[i] = v[i] * rs * w[d] * gamma[d] + beta[d];
        r[d] = hreg[i];
    }
    __syncthreads();

#pragma unroll
    for (int p = 0; p < NPASS_; p++) {
        const int ii = pi[p * P_ + tid];
        const int jj = pj[p * P_ + tid];
        const float ca = trig[p * (2 * P_) + tid];
        const float sa = trig[p * (2 * P_) + P_ + tid];
        const float hi = r[ii];
        const float hj = r[jj];
        r[ii] = hi * ca - hj * sa;     // pi/pj disjoint within a pass
        r[jj] = hi * sa + hj * ca;
        __syncthreads();
#pragma unroll
        for (int i = 0; i < 4; i++) {
            const int d = tid + i * 256;
            const float z = r[d] * gate[p * D_ + d] + bias[p * D_ + d];
            r[d] = z / (1.f + __expf(-z));
        }
        __syncthreads();
    }

    float* orow = out + (size_t)row * D_;
#pragma unroll
    for (int i = 0; i < 4; i++) {
        const int d = tid + i * 256;
        orow[d] = v[i] + r[d] - hreg[i];
    }
}

// ---------------- launch ----------------
extern "C" void kernel_launch(void* const* d_in, const int* in_sizes, int n_in,
                              void* d_out, int out_size) {
    const float* x      = (const float*)d_in[0];
    const float* gamma  = (const float*)d_in[1];
    const float* beta   = (const float*)d_in[2];
    const float* qkv_w  = (const float*)d_in[3];
    const float* o_w    = (const float*)d_in[4];
    const float* n1w    = (const float*)d_in[5];
    const float* n2w    = (const float*)d_in[6];
    const float* angles = (const float*)d_in[7];
    const float* gate   = (const float*)d_in[8];
    const float* bias   = (const float*)d_in[9];
    const int*   pi     = (const int*)d_in[10];
    const int*   pj     = (const int*)d_in[11];
    float* out = (float*)d_out;

    void *ph16, *pw16, *pqkv16, *patt16, *px2, *ptrig;
    cudaGetSymbolAddress(&ph16, g_h16);
    cudaGetSymbolAddress(&pw16, g_w16);
    cudaGetSymbolAddress(&pqkv16, g_qkv16);
    cudaGetSymbolAddress(&patt16, g_att16);
    cudaGetSymbolAddress(&px2, g_x2);
    cudaGetSymbolAddress(&ptrig, g_trig);
    half* h16   = (half*)ph16;
    half* w16   = (half*)pw16;       // [0, 3DD): qkv_w ; [3DD, 4DD): o_w
    half* qkv16 = (half*)pqkv16;
    half* att16 = (half*)patt16;
    float* x2   = (float*)px2;
    float* trig = (float*)ptrig;

    cudaFuncSetAttribute(gemm16_kernel<true, false>,
                         cudaFuncAttributeMaxDynamicSharedMemorySize, GT_SMEM);
    cudaFuncSetAttribute(gemm16_kernel<false, true>,
                         cudaFuncAttributeMaxDynamicSharedMemorySize, GT_SMEM);
    cudaFuncSetAttribute(attn16_kernel,
                         cudaFuncAttributeMaxDynamicSharedMemorySize, AT_SMEM);

    // trig tables + weight conversion
    trig_kernel<<<1, 256>>>(angles, trig);
    f2h4_kernel<<<(3 * D_ * D_ / 4 + 255) / 256, 256>>>(qkv_w, w16, 3 * D_ * D_ / 4);
    f2h4_kernel<<<(D_ * D_ / 4 + 255) / 256, 256>>>(o_w, w16 + 3 * D_ * D_, D_ * D_ / 4);

    // 1. h = rmsnorm(x, norm1_w) * gamma + beta  (fp16 out)
    rmsnorm_kernel<<<BT, 256>>>(x, n1w, gamma, beta, h16);

    // 2. qkv = h @ qkv_w^T  [4096 x 3072] fp16
    gemm16_kernel<true, false><<<dim3(3 * D_ / 128, BT / 128), 128, GT_SMEM>>>(
        h16, w16, nullptr, qkv16, 3 * D_, D_);

    // 3. causal flash attention
    attn16_kernel<<<dim3(T_ / 128, B_ * H_), 256, AT_SMEM>>>(qkv16, att16);

    // 4. x2 = x + attn @ o_w^T  [4096 x 1024] fp32
    gemm16_kernel<false, true><<<dim3(D_ / 128, BT / 128), 128, GT_SMEM>>>(
        att16, w16 + 3 * D_ * D_, x, x2, D_, D_);

    // 5+6. fused: rmsnorm2 -> rotation passes + silu -> out = x2 + r - h2
    rmsrot_kernel<<<BT, 256>>>(x2, n2w, gamma, beta, trig, gate, bias,
                               pi, pj, out);
}

// round 17
// speedup vs baseline: 1.5222x; 1.5222x over previous
#include <cuda_runtime.h>
#include <cuda_fp16.h>
#include <cstdint>
#include <math.h>

#define B_ 2
#define T_ 2048
#define D_ 1024
#define H_ 16
#define HD 64
#define P_ 256
#define NPASS_ 3
#define BT (B_ * T_)          // 4096

// ---------------- scratch (device globals; allocation-free) ----------------
__device__ __align__(16) half g_h16[BT * D_];          // rmsnorm1 out (fp16)
__device__ __align__(16) half g_w16[4 * D_ * D_];      // qkv_w (3DD) then o_w (DD), fp16
__device__ __align__(16) half g_qkv16[BT * 3 * D_];    // qkv projections fp16
__device__ __align__(16) half g_att16[BT * D_];        // attention out fp16
__device__ __align__(16) float g_x2[BT * D_];          // x + attn@o_w^T
__device__ __align__(16) float g_trig[2 * NPASS_ * P_]; // cos then sin per pass

// ---------------- helpers ----------------
__device__ __forceinline__ uint32_t smem_u32(const void* p) {
    return (uint32_t)__cvta_generic_to_shared(p);
}
__device__ __forceinline__ void ldm_x4(uint32_t& r0, uint32_t& r1, uint32_t& r2,
                                       uint32_t& r3, uint32_t addr) {
    asm volatile("ldmatrix.sync.aligned.m8n8.x4.shared.b16 {%0,%1,%2,%3},[%4];"
                 : "=r"(r0), "=r"(r1), "=r"(r2), "=r"(r3) : "r"(addr));
}
__device__ __forceinline__ void ldm_x4_t(uint32_t& r0, uint32_t& r1, uint32_t& r2,
                                         uint32_t& r3, uint32_t addr) {
    asm volatile("ldmatrix.sync.aligned.m8n8.x4.trans.shared.b16 {%0,%1,%2,%3},[%4];"
                 : "=r"(r0), "=r"(r1), "=r"(r2), "=r"(r3) : "r"(addr));
}
__device__ __forceinline__ void mma16816(float* c, const uint32_t* a, const uint32_t* b) {
    asm volatile(
        "mma.sync.aligned.m16n8k16.row.col.f32.f16.f16.f32 "
        "{%0,%1,%2,%3},{%4,%5,%6,%7},{%8,%9},{%0,%1,%2,%3};"
        : "+f"(c[0]), "+f"(c[1]), "+f"(c[2]), "+f"(c[3])
        : "r"(a[0]), "r"(a[1]), "r"(a[2]), "r"(a[3]), "r"(b[0]), "r"(b[1]));
}
__device__ __forceinline__ uint32_t h2u(float a, float b) {
    half2 h = __floats2half2_rn(a, b);
    uint32_t u;
    asm volatile("mov.b32 %0, %1;" : "=r"(u) : "r"(*reinterpret_cast<uint32_t*>(&h)));
    return u;
}
// single-MUFU base-2 exponential
__device__ __forceinline__ float ex2(float x) {
    float y;
    asm("ex2.approx.ftz.f32 %0, %1;" : "=f"(y) : "f"(x));
    return y;
}
__device__ __forceinline__ void cp16(uint32_t dst, const void* src) {
    asm volatile("cp.async.cg.shared.global [%0], [%1], 16;"
                 :: "r"(dst), "l"(src) : "memory");
}
__device__ __forceinline__ void cp16ca(uint32_t dst, const void* src) {
    asm volatile("cp.async.ca.shared.global [%0], [%1], 16;"
                 :: "r"(dst), "l"(src) : "memory");
}
__device__ __forceinline__ void cp_commit() {
    asm volatile("cp.async.commit_group;" ::: "memory");
}
template <int N>
__device__ __forceinline__ void cp_wait() {
    asm volatile("cp.async.wait_group %0;" :: "n"(N) : "memory");
}

// ---------------- precompute trig tables (768 sincosf total) ----------------
__global__ __launch_bounds__(256)
void trig_kernel(const float* __restrict__ angles, float* __restrict__ trig) {
    const int i = threadIdx.x;
#pragma unroll
    for (int p = 0; p < NPASS_; p++) {
        float sa, ca;
        sincosf(angles[p * P_ + i], &sa, &ca);
        trig[p * (2 * P_) + i] = ca;
        trig[p * (2 * P_) + P_ + i] = sa;
    }
}

// ---------------- f32 -> f16 conversion (weights) ----------------
__global__ __launch_bounds__(256)
void f2h4_kernel(const float* __restrict__ in, half* __restrict__ out, int n4) {
    int i = blockIdx.x * 256 + threadIdx.x;
    if (i < n4) {
        float4 v = ((const float4*)in)[i];
        half2* o = (half2*)out + i * 2;
        o[0] = __floats2half2_rn(v.x, v.y);
        o[1] = __floats2half2_rn(v.z, v.w);
    }
}

// ---------------- rmsnorm1 (+ gamma/beta), fp32 in, fp16 out ----------------
__global__ __launch_bounds__(256)
void rmsnorm_kernel(const float* __restrict__ x, const float* __restrict__ w,
                    const float* __restrict__ gamma, const float* __restrict__ beta,
                    half* __restrict__ out) {
    const int row = blockIdx.x;
    const int tid = threadIdx.x;
    const float* xr = x + (size_t)row * D_;
    float v[4];
    float ss = 0.f;
#pragma unroll
    for (int i = 0; i < 4; i++) {
        v[i] = xr[tid + i * 256];
        ss += v[i] * v[i];
    }
    __shared__ float red[8];
#pragma unroll
    for (int o = 16; o > 0; o >>= 1) ss += __shfl_xor_sync(0xffffffffu, ss, o);
    if ((tid & 31) == 0) red[tid >> 5] = ss;
    __syncthreads();
    if (tid < 8) {
        float s = red[tid];
#pragma unroll
        for (int o = 4; o > 0; o >>= 1) s += __shfl_xor_sync(0xffu, s, o);
        if (tid == 0) red[0] = s;
    }
    __syncthreads();
    const float rs = rsqrtf(red[0] * (1.0f / D_) + 1.1920929e-07f);
    half* op = out + (size_t)row * D_;
#pragma unroll
    for (int i = 0; i < 4; i++) {
        const int d = tid + i * 256;
        op[d] = (half)(v[i] * rs * w[d] * gamma[d] + beta[d]);
    }
}

// ---------------- fp16 NT GEMM with cp.async.ca 4-stage pipeline ------------
#define SA 40
#define GS 4
#define GT_SMEM (2 * GS * 128 * SA * 2)   // 81920 B
template <bool HALF_OUT, bool ADD_X>
__global__ __launch_bounds__(128, 2)
void gemm16_kernel(const half* __restrict__ A, const half* __restrict__ Bw,
                   const float* __restrict__ X, void* __restrict__ Cout,
                   int N, int K) {
    extern __shared__ char dsm[];
    half (*As)[128][SA] = (half(*)[128][SA])dsm;
    half (*Bs)[128][SA] = (half(*)[128][SA])(dsm + GS * 128 * SA * 2);
    const int tid = threadIdx.x, lane = tid & 31, w = tid >> 5;
    const int m0 = blockIdx.y * 128, n0 = blockIdx.x * 128;
    const int wm = (w >> 1) * 64, wn = (w & 1) * 64;
    const int lr = tid >> 1;
    const int lc = (tid & 1) * 16;
    const half* Ag0 = A + (size_t)(m0 + lr) * K + lc;
    const half* Ag1 = A + (size_t)(m0 + lr + 64) * K + lc;
    const half* Bg0 = Bw + (size_t)(n0 + lr) * K + lc;
    const half* Bg1 = Bw + (size_t)(n0 + lr + 64) * K + lc;

    auto issue = [&](int t) {
        const int s = t & (GS - 1);
        const int ko = t * 32;
        const uint32_t a0 = smem_u32(&As[s][lr][lc]);
        const uint32_t a1 = smem_u32(&As[s][lr + 64][lc]);
        const uint32_t b0 = smem_u32(&Bs[s][lr][lc]);
        const uint32_t b1 = smem_u32(&Bs[s][lr + 64][lc]);
        cp16ca(a0, Ag0 + ko);
        cp16ca(a0 + 16, Ag0 + ko + 8);
        cp16ca(a1, Ag1 + ko);
        cp16ca(a1 + 16, Ag1 + ko + 8);
        cp16ca(b0, Bg0 + ko);
        cp16ca(b0 + 16, Bg0 + ko + 8);
        cp16ca(b1, Bg1 + ko);
        cp16ca(b1 + 16, Bg1 + ko + 8);
    };

    float acc[4][8][4];
#pragma unroll
    for (int i = 0; i < 4; i++) {
#pragma unroll
        for (int j = 0; j < 8; j++) {
#pragma unroll
            for (int e = 0; e < 4; e++) acc[i][j][e] = 0.f;
        }
    }

    const int kt = K >> 5;
#pragma unroll
    for (int i = 0; i < GS - 1; i++) {
        issue(i);
        cp_commit();
    }

    for (int t = 0; t < kt; t++) {
        cp_wait<GS - 2>();
        __syncthreads();
        if (t + GS - 1 < kt) issue(t + GS - 1);
        cp_commit();
        const int cur = t & (GS - 1);
#pragma unroll
        for (int kk = 0; kk < 32; kk += 16) {
            uint32_t af[4][4];
            uint32_t bf[8][2];
#pragma unroll
            for (int mf = 0; mf < 4; mf++) {
                const int row = wm + mf * 16 + (lane & 15);
                const int col = kk + ((lane >> 4) << 3);
                ldm_x4(af[mf][0], af[mf][1], af[mf][2], af[mf][3],
                       smem_u32(&As[cur][row][col]));
            }
#pragma unroll
            for (int nf4 = 0; nf4 < 4; nf4++) {
                const int row = wn + nf4 * 16 + ((lane >> 4) << 3) + (lane & 7);
                const int col = kk + (((lane >> 3) & 1) << 3);
                uint32_t r0, r1, r2, r3;
                ldm_x4(r0, r1, r2, r3, smem_u32(&Bs[cur][row][col]));
                bf[nf4 * 2][0] = r0;
                bf[nf4 * 2][1] = r1;
                bf[nf4 * 2 + 1][0] = r2;
                bf[nf4 * 2 + 1][1] = r3;
            }
#pragma unroll
            for (int mf = 0; mf < 4; mf++) {
#pragma unroll
                for (int nf = 0; nf < 8; nf++) mma16816(acc[mf][nf], af[mf], bf[nf]);
            }
        }
    }

    const int r_lo = lane >> 2;
    const int c_off = (lane & 3) * 2;
#pragma unroll
    for (int mf = 0; mf < 4; mf++) {
        const int gr0 = m0 + wm + mf * 16 + r_lo;
        const int gr1 = gr0 + 8;
#pragma unroll
        for (int nf = 0; nf < 8; nf++) {
            const int gc = n0 + wn + nf * 8 + c_off;
            if constexpr (HALF_OUT) {
                half* C = (half*)Cout;
                *(half2*)(C + (size_t)gr0 * N + gc) =
                    __floats2half2_rn(acc[mf][nf][0], acc[mf][nf][1]);
                *(half2*)(C + (size_t)gr1 * N + gc) =
                    __floats2half2_rn(acc[mf][nf][2], acc[mf][nf][3]);
            } else {
                float* C = (float*)Cout;
                float v0 = acc[mf][nf][0];
                float v1 = acc[mf][nf][1];
                float v2 = acc[mf][nf][2];
                float v3 = acc[mf][nf][3];
                if constexpr (ADD_X) {
                    float2 x0 = *(const float2*)(X + (size_t)gr0 * N + gc);
                    float2 x1 = *(const float2*)(X + (size_t)gr1 * N + gc);
                    v0 += x0.x; v1 += x0.y; v2 += x1.x; v3 += x1.y;
                }
                *(float2*)(C + (size_t)gr0 * N + gc) = make_float2(v0, v1);
                *(float2*)(C + (size_t)gr1 * N + gc) = make_float2(v2, v3);
            }
        }
    }
}

// ---------------- fp16 causal flash attention, cp.async KV prefetch --------
#define AT_Q 0
#define AT_K 18432
#define AT_V 36864
#define AT_SMEM 55296
#define AT_ROWB 144            // 72 halfs * 2B
#define SC_LOG2E 0.1803368801111244f   // 0.125 * log2(e)

__global__ __launch_bounds__(256)
void attn16_kernel(const half* __restrict__ qkv, half* __restrict__ attno) {
    extern __shared__ char dsm[];
    const uint32_t sb = smem_u32(dsm);
    const int tid = threadIdx.x, lane = tid & 31, w = tid >> 5;
    const int q0 = blockIdx.x * 128;
    const int b = blockIdx.y >> 4, h = blockIdx.y & 15;
    const size_t rstride = 3 * D_;
    const half* qbase = qkv + (size_t)b * T_ * rstride + h * HD;

    auto issue_kv = [&](int t) {
        const int s = t & 1;
        const int k0 = t * 64;
#pragma unroll
        for (int i = 0; i < 2; i++) {
            const int idx = tid + i * 256;
            const int r = idx >> 3;
            const int c = (idx & 7) * 8;
            const half* kp = qbase + (size_t)(k0 + r) * rstride + D_ + c;
            cp16(sb + AT_K + s * 9216 + r * AT_ROWB + c * 2, kp);
            cp16(sb + AT_V + s * 9216 + r * AT_ROWB + c * 2, kp + D_);
        }
    };

#pragma unroll
    for (int i = 0; i < 4; i++) {
        const int idx = tid + i * 256;
        const int r = idx >> 3;
        const int c = (idx & 7) * 8;
        cp16(sb + AT_Q + r * AT_ROWB + c * 2,
             qbase + (size_t)(q0 + r) * rstride + c);
    }
    issue_kv(0);
    cp_commit();
    cp_wait<0>();
    __syncthreads();

    uint32_t qf[4][4];
    const int qrow = w * 16 + (lane & 15);
#pragma unroll
    for (int kk = 0; kk < 4; kk++) {
        const int col = kk * 16 + ((lane >> 4) << 3);
        ldm_x4(qf[kk][0], qf[kk][1], qf[kk][2], qf[kk][3],
               sb + AT_Q + qrow * AT_ROWB + col * 2);
    }

    float of[8][4];
#pragma unroll
    for (int nf = 0; nf < 8; nf++) {
#pragma unroll
        for (int e = 0; e < 4; e++) of[nf][e] = 0.f;
    }
    float m0 = -1e30f, m1 = -1e30f, l0 = 0.f, l1 = 0.f;
    const int r_lo = lane >> 2;
    const int c_off = (lane & 3) * 2;
    const int row0 = q0 + w * 16 + r_lo;

    const int nk = (q0 + 128) >> 6;
    for (int it = 0; it < nk; it++) {
        if (it > 0) {
            cp_wait<0>();
            __syncthreads();
        }
        if (it + 1 < nk) issue_kv(it + 1);
        cp_commit();
        const uint32_t kbase = sb + AT_K + (it & 1) * 9216;
        const uint32_t vbase = sb + AT_V + (it & 1) * 9216;
        const int k0 = it * 64;

        float sf[8][4];
#pragma unroll
        for (int nf = 0; nf < 8; nf++) {
#pragma unroll
            for (int e = 0; e < 4; e++) sf[nf][e] = 0.f;
        }
#pragma unroll
        for (int kk = 0; kk < 4; kk++) {
            uint32_t kf[8][2];
#pragma unroll
            for (int nf4 = 0; nf4 < 4; nf4++) {
                const int row = nf4 * 16 + ((lane >> 4) << 3) + (lane & 7);
                const int col = kk * 16 + (((lane >> 3) & 1) << 3);
                uint32_t r0, r1, r2, r3;
                ldm_x4(r0, r1, r2, r3, kbase + row * AT_ROWB + col * 2);
                kf[nf4 * 2][0] = r0;
                kf[nf4 * 2][1] = r1;
                kf[nf4 * 2 + 1][0] = r2;
                kf[nf4 * 2 + 1][1] = r3;
            }
#pragma unroll
            for (int nf = 0; nf < 8; nf++) mma16816(sf[nf], qf[kk], kf[nf]);
        }

        const bool domask = (k0 + 63 > row0);
#pragma unroll
        for (int nf = 0; nf < 8; nf++) {
#pragma unroll
            for (int e = 0; e < 4; e++) sf[nf][e] *= SC_LOG2E;
            if (domask) {
                const int col = k0 + nf * 8 + c_off;
                if (col > row0) sf[nf][0] = -1e30f;
                if (col + 1 > row0) sf[nf][1] = -1e30f;
                if (col > row0 + 8) sf[nf][2] = -1e30f;
                if (col + 1 > row0 + 8) sf[nf][3] = -1e30f;
            }
        }

        float mt0 = -1e30f, mt1 = -1e30f;
#pragma unroll
        for (int nf = 0; nf < 8; nf++) {
            mt0 = fmaxf(mt0, fmaxf(sf[nf][0], sf[nf][1]));
            mt1 = fmaxf(mt1, fmaxf(sf[nf][2], sf[nf][3]));
        }
        mt0 = fmaxf(mt0, __shfl_xor_sync(0xffffffffu, mt0, 1));
        mt0 = fmaxf(mt0, __shfl_xor_sync(0xffffffffu, mt0, 2));
        mt1 = fmaxf(mt1, __shfl_xor_sync(0xffffffffu, mt1, 1));
        mt1 = fmaxf(mt1, __shfl_xor_sync(0xffffffffu, mt1, 2));
        const float mn0 = fmaxf(m0, mt0);
        const float mn1 = fmaxf(m1, mt1);
        const float al0 = ex2(m0 - mn0);
        const float al1 = ex2(m1 - mn1);
        m0 = mn0;
        m1 = mn1;
        float rs0 = 0.f, rs1 = 0.f;
#pragma unroll
        for (int nf = 0; nf < 8; nf++) {
            sf[nf][0] = ex2(sf[nf][0] - mn0);
            sf[nf][1] = ex2(sf[nf][1] - mn0);
            sf[nf][2] = ex2(sf[nf][2] - mn1);
            sf[nf][3] = ex2(sf[nf][3] - mn1);
            rs0 += sf[nf][0] + sf[nf][1];
            rs1 += sf[nf][2] + sf[nf][3];
        }
        l0 = l0 * al0 + rs0;
        l1 = l1 * al1 + rs1;
#pragma unroll
        for (int nf = 0; nf < 8; nf++) {
            of[nf][0] *= al0;
            of[nf][1] *= al0;
            of[nf][2] *= al1;
            of[nf][3] *= al1;
        }

        uint32_t pf[4][4];
#pragma unroll
        for (int kk = 0; kk < 4; kk++) {
            pf[kk][0] = h2u(sf[2 * kk][0], sf[2 * kk][1]);
            pf[kk][1] = h2u(sf[2 * kk][2], sf[2 * kk][3]);
            pf[kk][2] = h2u(sf[2 * kk + 1][0], sf[2 * kk + 1][1]);
            pf[kk][3] = h2u(sf[2 * kk + 1][2], sf[2 * kk + 1][3]);
        }

#pragma unroll
        for (int kk = 0; kk < 4; kk++) {
            uint32_t vf[8][2];
#pragma unroll
            for (int nf4 = 0; nf4 < 4; nf4++) {
                const int row = kk * 16 + (lane & 15);
                const int col = nf4 * 16 + ((lane >> 4) << 3);
                uint32_t r0, r1, r2, r3;
                ldm_x4_t(r0, r1, r2, r3, vbase + row * AT_ROWB + col * 2);
                vf[nf4 * 2][0] = r0;
                vf[nf4 * 2][1] = r1;
                vf[nf4 * 2 + 1][0] = r2;
                vf[nf4 * 2 + 1][1] = r3;
            }
#pragma unroll
            for (int nf = 0; nf < 8; nf++) mma16816(of[nf], pf[kk], vf[nf]);
        }
    }

    l0 += __shfl_xor_sync(0xffffffffu, l0, 1);
    l0 += __shfl_xor_sync(0xffffffffu, l0, 2);
    l1 += __shfl_xor_sync(0xffffffffu, l1, 1);
    l1 += __shfl_xor_sync(0xffffffffu, l1, 2);

    const float inv0 = 1.f / l0;
    const float inv1 = 1.f / l1;
    half* obase = attno + h * HD;
#pragma unroll
    for (int nf = 0; nf < 8; nf++) {
        const int c = nf * 8 + c_off;
        *(half2*)(obase + ((size_t)b * T_ + row0) * D_ + c) =
            __floats2half2_rn(of[nf][0] * inv0, of[nf][1] * inv0);
        *(half2*)(obase + ((size_t)b * T_ + row0 + 8) * D_ + c) =
            __floats2half2_rn(of[nf][2] * inv1, of[nf][3] * inv1);
    }
}

// ------- fused rmsnorm2 + rotation passes + silu + final combine -----------
// Trig from precomputed table (no sincosf in the hot path).
__global__ __launch_bounds__(256)
void rmsrot_kernel(const float* __restrict__ x2, const float* __restrict__ w,
                   const float* __restrict__ gamma, const float* __restrict__ beta,
                   const float* __restrict__ trig, const float* __restrict__ gate,
                   const float* __restrict__ bias, const int* __restrict__ pi,
                   const int* __restrict__ pj, float* __restrict__ out) {
    const int row = blockIdx.x;
    const int tid = threadIdx.x;
    __shared__ float r[D_];
    __shared__ float red[8];
    const float* xrow = x2 + (size_t)row * D_;

    float v[4];
    float ss = 0.f;
#pragma unroll
    for (int i = 0; i < 4; i++) {
        v[i] = xrow[tid + i * 256];
        ss += v[i] * v[i];
    }
#pragma unroll
    for (int o = 16; o > 0; o >>= 1) ss += __shfl_xor_sync(0xffffffffu, ss, o);
    if ((tid & 31) == 0) red[tid >> 5] = ss;
    __syncthreads();
    if (tid < 8) {
        float s = red[tid];
#pragma unroll
        for (int o = 4; o > 0; o >>= 1) s += __shfl_xor_sync(0xffu, s, o);
        if (tid == 0) red[0] = s;
    }
    __syncthreads();
    const float rs = rsqrtf(red[0] * (1.0f / D_) + 1.1920929e-07f);

    float hreg[4];
#pragma unroll
    for (int i = 0; i < 4; i++) {
        const int d = tid + i * 256;
        hreg[i] = v[i] * rs * w[d] * gamma[d] + beta[d];
        r[d] = hreg[i];
    }
    __syncthreads();

#pragma unroll
    for (int p = 0; p < NPASS_; p++) {
        const int ii = pi[p * P_ + tid];
        const int jj = pj[p * P_ + tid];
        const float ca = trig[p * (2 * P_) + tid];
        const float sa = trig[p * (2 * P_) + P_ + tid];
        const float hi = r[ii];
        const float hj = r[jj];
        r[ii] = hi * ca - hj * sa;     // pi/pj disjoint within a pass
        r[jj] = hi * sa + hj * ca;
        __syncthreads();
#pragma unroll
        for (int i = 0; i < 4; i++) {
            const int d = tid + i * 256;
            const float z = r[d] * gate[p * D_ + d] + bias[p * D_ + d];
            r[d] = z / (1.f + __expf(-z));
        }
        __syncthreads();
    }

    float* orow = out + (size_t)row * D_;
#pragma unroll
    for (int i = 0; i < 4; i++) {
        const int d = tid + i * 256;
        orow[d] = v[i] + r[d] - hreg[i];
    }
}

// ---------------- launch ----------------
extern "C" void kernel_launch(void* const* d_in, const int* in_sizes, int n_in,
                              void* d_out, int out_size) {
    const float* x      = (const float*)d_in[0];
    const float* gamma  = (const float*)d_in[1];
    const float* beta   = (const float*)d_in[2];
    const float* qkv_w  = (const float*)d_in[3];
    const float* o_w    = (const float*)d_in[4];
    const float* n1w    = (const float*)d_in[5];
    const float* n2w    = (const float*)d_in[6];
    const float* angles = (const float*)d_in[7];
    const float* gate   = (const float*)d_in[8];
    const float* bias   = (const float*)d_in[9];
    const int*   pi     = (const int*)d_in[10];
    const int*   pj     = (const int*)d_in[11];
    float* out = (float*)d_out;

    void *ph16, *pw16, *pqkv16, *patt16, *px2, *ptrig;
    cudaGetSymbolAddress(&ph16, g_h16);
    cudaGetSymbolAddress(&pw16, g_w16);
    cudaGetSymbolAddress(&pqkv16, g_qkv16);
    cudaGetSymbolAddress(&patt16, g_att16);
    cudaGetSymbolAddress(&px2, g_x2);
    cudaGetSymbolAddress(&ptrig, g_trig);
    half* h16   = (half*)ph16;
    half* w16   = (half*)pw16;       // [0, 3DD): qkv_w ; [3DD, 4DD): o_w
    half* qkv16 = (half*)pqkv16;
    half* att16 = (half*)patt16;
    float* x2   = (float*)px2;
    float* trig = (float*)ptrig;

    cudaFuncSetAttribute(gemm16_kernel<true, false>,
                         cudaFuncAttributeMaxDynamicSharedMemorySize, GT_SMEM);
    cudaFuncSetAttribute(gemm16_kernel<false, true>,
                         cudaFuncAttributeMaxDynamicSharedMemorySize, GT_SMEM);
    cudaFuncSetAttribute(attn16_kernel,
                         cudaFuncAttributeMaxDynamicSharedMemorySize, AT_SMEM);

    // trig tables + weight conversion
    trig_kernel<<<1, 256>>>(angles, trig);
    f2h4_kernel<<<(3 * D_ * D_ / 4 + 255) / 256, 256>>>(qkv_w, w16, 3 * D_ * D_ / 4);
    f2h4_kernel<<<(D_ * D_ / 4 + 255) / 256, 256>>>(o_w, w16 + 3 * D_ * D_, D_ * D_ / 4);

    // 1. h = rmsnorm(x, norm1_w) * gamma + beta  (fp16 out)
    rmsnorm_kernel<<<BT, 256>>>(x, n1w, gamma, beta, h16);

    // 2. qkv = h @ qkv_w^T  [4096 x 3072] fp16
    gemm16_kernel<true, false><<<dim3(3 * D_ / 128, BT / 128), 128, GT_SMEM>>>(
        h16, w16, nullptr, qkv16, 3 * D_, D_);

    // 3. causal flash attention
    attn16_kernel<<<dim3(T_ / 128, B_ * H_), 256, AT_SMEM>>>(qkv16, att16);

    // 4. x2 = x + attn @ o_w^T  [4096 x 1024] fp32
    gemm16_kernel<false, true><<<dim3(D_ / 128, BT / 128), 128, GT_SMEM>>>(
        att16, w16 + 3 * D_ * D_, x, x2, D_, D_);

    // 5+6. fused: rmsnorm2 -> rotation passes + silu -> out = x2 + r - h2
    rmsrot_kernel<<<BT, 256>>>(x2, n2w, gamma, beta, trig, gate, bias,
                               pi, pj, out);
}